// round 16
// baseline (speedup 1.0000x reference)
#include <cuda_runtime.h>
#include <math.h>

#define BB 32
#define TT 512
#define FF 128
#define RR 2048
#define C1 0.05f
#define C2 0.95f

#define NCTA 128
#define ROWS_PER_CTA 16
#define NTHREADS 256            // 8 warps, 2 per SMSP
#define WQ 513                  // W row stride in quads
#define SQ 65                   // staging batch-row stride in quads

__device__ float g_state[2][BB * RR];
__device__ unsigned int g_bar;

// ---------------------------------------------------------------------------
// IDENTIFIED REFERENCE RECIPE (verified rel_err = 0.0):
//   gemm: fp32 splitK=4 — 4 k-slices of 512; each slice a serial FMA chain
//         from zero, k ascending; slice partials folded by ascending fadds.
//   z = fadd(acc, u); tanh = XLA EmitFastTanh (clamp ±7.99881172180175781,
//   FMA Cephes, IEEE div); upd = fmaf(C1, s, C2*th); u = serial f-chain + bias.
// ---------------------------------------------------------------------------
__device__ __forceinline__ float fast_tanh_B(float x) {
    const float cl = 7.99881172180175781f;
    float xc = fminf(fmaxf(x, -cl), cl);
    float x2 = __fmul_rn(xc, xc);
    float p = -2.76076847742355e-16f;
    p = fmaf(x2, p, 2.00018790482477e-13f);
    p = fmaf(x2, p, -8.60467152213735e-11f);
    p = fmaf(x2, p, 5.12229709037114e-08f);
    p = fmaf(x2, p, 1.48572235717979e-05f);
    p = fmaf(x2, p, 6.37261928875436e-04f);
    p = fmaf(x2, p, 4.89352455891786e-03f);
    float num = __fmul_rn(xc, p);
    float q = 1.19825839466702e-06f;
    q = fmaf(x2, q, 1.18534705686654e-04f);
    q = fmaf(x2, q, 2.26843463243900e-03f);
    q = fmaf(x2, q, 4.89352518554385e-03f);
    float r = __fdiv_rn(num, q);
    return (fabsf(x) < 0.0004f) ? x : r;
}
__device__ __forceinline__ float do_upd(float s, float th) {
    return fmaf(C1, s, __fmul_rn(C2, th));
}

__device__ __forceinline__ unsigned smem_addr_u32(const void* p) {
    unsigned r;
    asm("{ .reg .u64 t; cvta.to.shared.u64 t, %1; cvt.u32.u64 %0, t; }"
        : "=r"(r) : "l"(p));
    return r;
}
__device__ __forceinline__ void cp_async16(unsigned dst, const void* src) {
    asm volatile("cp.async.cg.shared.global [%0], [%1], 16;"
                 :: "r"(dst), "l"(src));
}

// ---------------------------------------------------------------------------
// Fused init + u projection (u[bt][r] = serial f-chain + bias).
// ---------------------------------------------------------------------------
#define XS_STRIDE 33
#define WS_STRIDE4 33

__global__ void __launch_bounds__(256) input_gemm_strict(
    const float* __restrict__ x, const float* __restrict__ Win,
    const float* __restrict__ bias, const float* __restrict__ state0,
    float* __restrict__ out) {
    extern __shared__ float sm[];
    float4* xs4 = reinterpret_cast<float4*>(sm);
    float4* ws4 = reinterpret_cast<float4*>(sm) + 32 * XS_STRIDE;

    const int tid = threadIdx.x;
    const int bt0 = blockIdx.x * 32;

    if (blockIdx.x == 0 && tid == 0) g_bar = 0u;
    {
        int idx = blockIdx.x * 128 + tid;
        if (tid < 128) g_state[0][idx] = state0[idx & (RR - 1)];
    }

    const float4* xg4 = reinterpret_cast<const float4*>(x);
    #pragma unroll
    for (int it = 0; it < 4; ++it) {
        int L = it * 256 + tid;
        int row = L >> 5, c = L & 31;
        xs4[row * XS_STRIDE + c] = xg4[(size_t)(bt0 + row) * 32 + c];
    }

    const int btl = tid >> 3;
    const int rg = tid & 7;
    const float4* wg4 = reinterpret_cast<const float4*>(Win);

    for (int rt = 0; rt < RR; rt += 64) {
        __syncthreads();
        #pragma unroll
        for (int it = 0; it < 8; ++it) {
            int L = it * 256 + tid;
            int row = L >> 5, c = L & 31;
            ws4[row * WS_STRIDE4 + c] = wg4[(size_t)(rt + row) * 32 + c];
        }
        __syncthreads();

        float acc[8];
        #pragma unroll
        for (int j = 0; j < 8; ++j) acc[j] = 0.0f;

        #pragma unroll 8
        for (int fq = 0; fq < 32; ++fq) {
            float4 xq = xs4[btl * XS_STRIDE + fq];
            #pragma unroll
            for (int j = 0; j < 8; ++j) {
                float4 wq = ws4[(rg * 8 + j) * WS_STRIDE4 + fq];
                float a = acc[j];
                a = fmaf(xq.x, wq.x, a);
                a = fmaf(xq.y, wq.y, a);
                a = fmaf(xq.z, wq.z, a);
                a = fmaf(xq.w, wq.w, a);
                acc[j] = a;
            }
        }
        #pragma unroll
        for (int j = 0; j < 8; ++j) {
            int r = rt + rg * 8 + j;
            out[(size_t)(bt0 + btl) * RR + r] = __fadd_rn(acc[j], bias[r]);
        }
    }
}

// ---------------------------------------------------------------------------
// Persistent scan. 128 CTAs x 256 threads (2 warps/SMSP for latency cover).
// Thread tile: rows {rh, rh+8} x batch bh (2 outputs, 2 chains).
// Warp w stages ONLY batches 4w..4w+3 (its lanes' batches) -> __syncwarp only.
// Slice = 512 floats = 2 chunks; fold after odd chunks (exact recipe order).
// ---------------------------------------------------------------------------
__global__ void __launch_bounds__(NTHREADS) recurrent_kernel(
    const float* __restrict__ Wrec, float* __restrict__ out) {
    extern __shared__ float4 smq[];
    float4* wsm4 = smq;                      // 16 x 513 quads
    float4* sbuf = smq + ROWS_PER_CTA * WQ;  // 2 x 32 x 65 quads

    const int tid = threadIdx.x;
    const int lane = tid & 31;
    const int warp = tid >> 5;
    const int cta = blockIdx.x;
    const int rbase = cta * ROWS_PER_CTA;

    const float4* W4 = reinterpret_cast<const float4*>(Wrec);
    for (int L = tid; L < ROWS_PER_CTA * (RR / 4); L += NTHREADS) {
        int row = L >> 9, c = L & 511;
        wsm4[row * WQ + c] = W4[(size_t)(rbase + row) * (RR / 4) + c];
    }

    const int rh = tid & 7;
    const int bh = tid >> 3;           // 0..31 (batch)
    const int r0 = rbase + rh, r1 = rbase + rh + 8;
    const int wb = warp * 4;           // this warp's first staged batch
    const unsigned sbuf_base = smem_addr_u32(sbuf);

    __syncthreads();   // W visible

    int par = 0;
    for (int t = 0; t < TT; ++t) {
        const float* scur = g_state[par];
        float* snxt = g_state[par ^ 1];
        const float4* s4g = reinterpret_cast<const float4*>(scur);

        // Prefetch u and s_old (consumed only in the epilogue)
        size_t o0 = ((size_t)bh * TT + t) * RR + r0;
        size_t o1 = ((size_t)bh * TT + t) * RR + r1;
        float u0 = out[o0], u1 = out[o1];
        float so0 = __ldcg(&scur[bh * RR + r0]);
        float so1 = __ldcg(&scur[bh * RR + r1]);

        // Stage chunk 0 (warp-private batches 4w..4w+3) into buffer 0
        #pragma unroll
        for (int it = 0; it < 8; ++it) {
            int L = it * 32 + lane;            // 0..255
            int b = wb + (L >> 6), c = L & 63;
            unsigned dst = sbuf_base + (unsigned)(b * SQ + c) * 16u;
            cp_async16(dst, &s4g[(size_t)b * (RR / 4) + c]);
        }
        asm volatile("cp.async.commit_group;");
        asm volatile("cp.async.wait_group 0;" ::: "memory");
        __syncwarp();

        float a0 = 0.f, a1 = 0.f;   // folded slice partials
        float p0 = 0.f, p1 = 0.f;   // current slice chains

        #pragma unroll 1
        for (int ch = 0; ch < 8; ++ch) {
            const int cur = ch & 1;
            if (ch < 7) {   // prefetch next chunk into the other buffer
                const int nb = cur ^ 1;
                #pragma unroll
                for (int it = 0; it < 8; ++it) {
                    int L = it * 32 + lane;
                    int b = wb + (L >> 6), c = L & 63;
                    unsigned dst = sbuf_base +
                        (unsigned)(nb * 32 * SQ + b * SQ + c) * 16u;
                    cp_async16(dst, &s4g[(size_t)b * (RR / 4) + (ch + 1) * 64 + c]);
                }
                asm volatile("cp.async.commit_group;");
            }

            const float4* wr0 = wsm4 + rh * WQ + ch * 64;
            const float4* wr1 = wsm4 + (rh + 8) * WQ + ch * 64;
            const float4* sb = sbuf + cur * 32 * SQ + bh * SQ;

            #pragma unroll 8
            for (int kq = 0; kq < 64; ++kq) {
                float4 w0 = wr0[kq];
                float4 w1 = wr1[kq];
                float4 s = sb[kq];
                p0 = fmaf(w0.x, s.x, p0);
                p0 = fmaf(w0.y, s.y, p0);
                p0 = fmaf(w0.z, s.z, p0);
                p0 = fmaf(w0.w, s.w, p0);
                p1 = fmaf(w1.x, s.x, p1);
                p1 = fmaf(w1.y, s.y, p1);
                p1 = fmaf(w1.z, s.z, p1);
                p1 = fmaf(w1.w, s.w, p1);
            }

            if (ch & 1) {    // end of 512-float slice: ascending fold
                a0 = __fadd_rn(a0, p0); p0 = 0.f;
                a1 = __fadd_rn(a1, p1); p1 = 0.f;
            }

            asm volatile("cp.async.wait_group 0;" ::: "memory");
            __syncwarp();
        }

        // Epilogue (exact recipe per output)
        {
            float z, th, sn;
            z = __fadd_rn(a0, u0); th = fast_tanh_B(z); sn = do_upd(so0, th);
            out[o0] = sn; snxt[bh * RR + r0] = sn;
            z = __fadd_rn(a1, u1); th = fast_tanh_B(z); sn = do_upd(so1, th);
            out[o1] = sn; snxt[bh * RR + r1] = sn;
        }

        // Grid barrier (CG pattern: bar.sync; tid0 release-add + acquire spin)
        __syncthreads();
        if (tid == 0) {
            asm volatile("red.release.gpu.global.add.u32 [%0], %1;"
                         :: "l"(&g_bar), "r"(1u) : "memory");
            unsigned target = (unsigned)(t + 1) * NCTA;
            unsigned v;
            do {
                asm volatile("ld.acquire.gpu.global.u32 %0, [%1];"
                             : "=r"(v) : "l"(&g_bar) : "memory");
                if (v >= target) break;
                __nanosleep(24);
            } while (true);
        }
        __syncthreads();

        par ^= 1;
    }
}

// ---------------------------------------------------------------------------
extern "C" void kernel_launch(void* const* d_in, const int* in_sizes, int n_in,
                              void* d_out, int out_size) {
    const float* x      = (const float*)d_in[0];
    const float* Win    = (const float*)d_in[1];
    const float* Wrec   = (const float*)d_in[2];
    const float* bias   = (const float*)d_in[3];
    const float* state0 = (const float*)d_in[4];
    float* out = (float*)d_out;

    int smem_gemm = (32 * XS_STRIDE + 64 * WS_STRIDE4) * 16;
    int smem_rec  = (ROWS_PER_CTA * WQ + 2 * 32 * SQ) * 16;   // ~193.3 KB

    cudaFuncSetAttribute(input_gemm_strict, cudaFuncAttributeMaxDynamicSharedMemorySize, smem_gemm);
    cudaFuncSetAttribute(recurrent_kernel, cudaFuncAttributeMaxDynamicSharedMemorySize, smem_rec);

    input_gemm_strict<<<(BB * TT) / 32, 256, smem_gemm>>>(x, Win, bias, state0, out);

    recurrent_kernel<<<NCTA, NTHREADS, smem_rec>>>(Wrec, out);
}

// round 17
// speedup vs baseline: 1.5102x; 1.5102x over previous
#include <cuda_runtime.h>
#include <math.h>

#define BB 32
#define TT 512
#define FF 128
#define RR 2048
#define C1 0.05f
#define C2 0.95f

#define NCTA 128
#define ROWS_PER_CTA 16
#define NTHREADS 128            // 4 warps; warp w owns splitK slice w

__device__ float g_state[2][BB * RR];
__device__ unsigned int g_bar;

// ---------------------------------------------------------------------------
// IDENTIFIED REFERENCE RECIPE (verified rel_err = 0.0):
//   gemm: fp32 splitK=4 — 4 k-slices of 512; each slice a serial FMA chain
//         from zero, k ascending; partials folded acc=0; acc=fadd(acc,s_i)
//         in ascending slice order.
//   z = fadd(acc, u); tanh = XLA EmitFastTanh (clamp ±7.99881172180175781,
//   FMA Cephes, IEEE div); upd = fmaf(C1, s, C2*th); u = serial f-chain + bias.
// ---------------------------------------------------------------------------
__device__ __forceinline__ float fast_tanh_B(float x) {
    const float cl = 7.99881172180175781f;
    float xc = fminf(fmaxf(x, -cl), cl);
    float x2 = __fmul_rn(xc, xc);
    float p = -2.76076847742355e-16f;
    p = fmaf(x2, p, 2.00018790482477e-13f);
    p = fmaf(x2, p, -8.60467152213735e-11f);
    p = fmaf(x2, p, 5.12229709037114e-08f);
    p = fmaf(x2, p, 1.48572235717979e-05f);
    p = fmaf(x2, p, 6.37261928875436e-04f);
    p = fmaf(x2, p, 4.89352455891786e-03f);
    float num = __fmul_rn(xc, p);
    float q = 1.19825839466702e-06f;
    q = fmaf(x2, q, 1.18534705686654e-04f);
    q = fmaf(x2, q, 2.26843463243900e-03f);
    q = fmaf(x2, q, 4.89352518554385e-03f);
    float r = __fdiv_rn(num, q);
    return (fabsf(x) < 0.0004f) ? x : r;
}
__device__ __forceinline__ float do_upd(float s, float th) {
    return fmaf(C1, s, __fmul_rn(C2, th));
}

__device__ __forceinline__ unsigned smem_addr_u32(const void* p) {
    unsigned r;
    asm("{ .reg .u64 t; cvta.to.shared.u64 t, %1; cvt.u32.u64 %0, t; }"
        : "=r"(r) : "l"(p));
    return r;
}
__device__ __forceinline__ void cp_async16(unsigned dst, const void* src) {
    asm volatile("cp.async.cg.shared.global [%0], [%1], 16;"
                 :: "r"(dst), "l"(src));
}

// ---------------------------------------------------------------------------
// Fused init + u projection (u[bt][r] = serial f-chain + bias). Unchanged.
// ---------------------------------------------------------------------------
#define XS_STRIDE 33
#define WS_STRIDE4 33

__global__ void __launch_bounds__(256) input_gemm_strict(
    const float* __restrict__ x, const float* __restrict__ Win,
    const float* __restrict__ bias, const float* __restrict__ state0,
    float* __restrict__ out) {
    extern __shared__ float sm[];
    float4* xs4 = reinterpret_cast<float4*>(sm);
    float4* ws4 = reinterpret_cast<float4*>(sm) + 32 * XS_STRIDE;

    const int tid = threadIdx.x;
    const int bt0 = blockIdx.x * 32;

    if (blockIdx.x == 0 && tid == 0) g_bar = 0u;
    {
        int idx = blockIdx.x * 128 + tid;
        if (tid < 128) g_state[0][idx] = state0[idx & (RR - 1)];
    }

    const float4* xg4 = reinterpret_cast<const float4*>(x);
    #pragma unroll
    for (int it = 0; it < 4; ++it) {
        int L = it * 256 + tid;
        int row = L >> 5, c = L & 31;
        xs4[row * XS_STRIDE + c] = xg4[(size_t)(bt0 + row) * 32 + c];
    }

    const int btl = tid >> 3;
    const int rg = tid & 7;
    const float4* wg4 = reinterpret_cast<const float4*>(Win);

    for (int rt = 0; rt < RR; rt += 64) {
        __syncthreads();
        #pragma unroll
        for (int it = 0; it < 8; ++it) {
            int L = it * 256 + tid;
            int row = L >> 5, c = L & 31;
            ws4[row * WS_STRIDE4 + c] = wg4[(size_t)(rt + row) * 32 + c];
        }
        __syncthreads();

        float acc[8];
        #pragma unroll
        for (int j = 0; j < 8; ++j) acc[j] = 0.0f;

        #pragma unroll 8
        for (int fq = 0; fq < 32; ++fq) {
            float4 xq = xs4[btl * XS_STRIDE + fq];
            #pragma unroll
            for (int j = 0; j < 8; ++j) {
                float4 wq = ws4[(rg * 8 + j) * WS_STRIDE4 + fq];
                float a = acc[j];
                a = fmaf(xq.x, wq.x, a);
                a = fmaf(xq.y, wq.y, a);
                a = fmaf(xq.z, wq.z, a);
                a = fmaf(xq.w, wq.w, a);
                acc[j] = a;
            }
        }
        #pragma unroll
        for (int j = 0; j < 8; ++j) {
            int r = rt + rg * 8 + j;
            out[(size_t)(bt0 + btl) * RR + r] = __fadd_rn(acc[j], bias[r]);
        }
    }
}

// ---------------------------------------------------------------------------
// Persistent scan. 128 CTAs x 128 threads (4 warps).
// Warp w computes splitK slice w (k in [512w, 512w+512)) for ALL 512 outputs.
// Thread tile: rows {rg,rg+4,rg+8,rg+12} x batches {bg,bg+8,bg+16,bg+24}
// (rg = lane&3, bg = lane>>2) -> 16 chains per thread.
// W smem: XOR swizzle quad = row*512 + (kq ^ (row&7))  (conflict-free).
// s: warp-private double-buffered 16-quad sub-chunks via cp.async.cg,
//    quad = b*16 + (q ^ (b&7)).
// Step end: slice partials folded across warps via smem in ascending slice
// order with acc starting at 0 (bit-exact recipe).
// ---------------------------------------------------------------------------
__global__ void __launch_bounds__(NTHREADS) recurrent_kernel(
    const float* __restrict__ Wrec, float* __restrict__ out) {
    extern __shared__ float4 smq[];
    float4* Wsm = smq;                     // 16 x 512 quads (128 KB)
    float4* Stg = smq + 16 * 512;          // 4 warps x 2 bufs x 512 quads (64 KB)
    float* Psm = reinterpret_cast<float*>(Stg);  // fold area (aliases Stg)

    const int tid = threadIdx.x;
    const int lane = tid & 31;
    const int warp = tid >> 5;             // slice index
    const int cta = blockIdx.x;
    const int rbase = cta * ROWS_PER_CTA;

    // Load W slice, XOR-swizzled
    const float4* W4 = reinterpret_cast<const float4*>(Wrec);
    for (int L = tid; L < ROWS_PER_CTA * 512; L += NTHREADS) {
        int row = L >> 9, kq = L & 511;
        Wsm[row * 512 + (kq ^ (row & 7))] = W4[(size_t)(rbase + row) * 512 + kq];
    }

    const int rg = lane & 3;
    const int bg = lane >> 2;              // 0..7
    const int xw0 = rg, xw1 = rg + 4;      // W xor masks for j even/odd
    // epilogue mapping: batch eb, rows rbase + err + 4k
    const int err = lane & 3;
    const int eb = 8 * warp + (lane >> 2);
    const unsigned stg_base = smem_addr_u32(Stg) + (unsigned)warp * 1024u * 16u;

    __syncthreads();

    int par = 0;
    for (int t = 0; t < TT; ++t) {
        const float* scur = g_state[par];
        float* snxt = g_state[par ^ 1];
        const float4* s4g = reinterpret_cast<const float4*>(scur);

        // Prefetch epilogue operands (coalesced: quarter-warp = consecutive r)
        size_t oidx[4];
        float uo[4], so[4];
        #pragma unroll
        for (int k = 0; k < 4; ++k) {
            int r = rbase + err + 4 * k;
            oidx[k] = ((size_t)eb * TT + t) * RR + r;
            uo[k] = out[oidx[k]];
            so[k] = __ldcg(&scur[eb * RR + r]);
        }

        // Stage sub-chunk 0 of this warp's slice into buffer 0
        {
            const int kq0 = warp * 128;
            #pragma unroll
            for (int it = 0; it < 16; ++it) {
                int L = it * 32 + lane;          // 0..511
                int b = L >> 4, q = L & 15;
                unsigned dst = stg_base + (unsigned)(b * 16 + (q ^ (b & 7))) * 16u;
                cp_async16(dst, &s4g[(size_t)b * 512 + kq0 + q]);
            }
            asm volatile("cp.async.commit_group;");
        }

        float p[16];
        #pragma unroll
        for (int i = 0; i < 16; ++i) p[i] = 0.0f;

        #pragma unroll 1
        for (int sub = 0; sub < 8; ++sub) {
            if (sub < 7) {   // prefetch next sub-chunk into other buffer
                const int nb = (sub + 1) & 1;
                const int kq0 = warp * 128 + (sub + 1) * 16;
                #pragma unroll
                for (int it = 0; it < 16; ++it) {
                    int L = it * 32 + lane;
                    int b = L >> 4, q = L & 15;
                    unsigned dst = stg_base +
                        (unsigned)(nb * 512 + b * 16 + (q ^ (b & 7))) * 16u;
                    cp_async16(dst, &s4g[(size_t)b * 512 + kq0 + q]);
                }
                asm volatile("cp.async.commit_group;");
                asm volatile("cp.async.wait_group 1;" ::: "memory");
            } else {
                asm volatile("cp.async.wait_group 0;" ::: "memory");
            }
            __syncwarp();

            const float4* sb = Stg + warp * 1024 + (sub & 1) * 512;
            const int kqg = warp * 128 + sub * 16;
            const float4* Wp0 = Wsm + (rg + 0) * 512 + kqg;
            const float4* Wp1 = Wsm + (rg + 4) * 512 + kqg;
            const float4* Wp2 = Wsm + (rg + 8) * 512 + kqg;
            const float4* Wp3 = Wsm + (rg + 12) * 512 + kqg;
            const float4* Sp0 = sb + (bg + 0) * 16;
            const float4* Sp1 = sb + (bg + 8) * 16;
            const float4* Sp2 = sb + (bg + 16) * 16;
            const float4* Sp3 = sb + (bg + 24) * 16;

            #pragma unroll 4
            for (int q = 0; q < 16; ++q) {
                float4 w0 = Wp0[q ^ xw0];
                float4 w1 = Wp1[q ^ xw1];
                float4 w2 = Wp2[q ^ xw0];
                float4 w3 = Wp3[q ^ xw1];
                float4 s0 = Sp0[q ^ bg];
                float4 s1 = Sp1[q ^ bg];
                float4 s2 = Sp2[q ^ bg];
                float4 s3 = Sp3[q ^ bg];
                // 16 chains: p[i*4+j] for batch i, row j
                #define FMA4(acc, W, S) \
                    acc = fmaf((W).x, (S).x, acc); \
                    acc = fmaf((W).y, (S).y, acc); \
                    acc = fmaf((W).z, (S).z, acc); \
                    acc = fmaf((W).w, (S).w, acc);
                FMA4(p[0],  w0, s0) FMA4(p[1],  w1, s0)
                FMA4(p[2],  w2, s0) FMA4(p[3],  w3, s0)
                FMA4(p[4],  w0, s1) FMA4(p[5],  w1, s1)
                FMA4(p[6],  w2, s1) FMA4(p[7],  w3, s1)
                FMA4(p[8],  w0, s2) FMA4(p[9],  w1, s2)
                FMA4(p[10], w2, s2) FMA4(p[11], w3, s2)
                FMA4(p[12], w0, s3) FMA4(p[13], w1, s3)
                FMA4(p[14], w2, s3) FMA4(p[15], w3, s3)
                #undef FMA4
            }
            __syncwarp();   // protect buffer from next prefetch overwrite
        }

        // All slices done: publish partials, fold across warps (ascending).
        __syncthreads();
        #pragma unroll
        for (int i = 0; i < 4; ++i) {
            #pragma unroll
            for (int j = 0; j < 4; ++j) {
                int o = (rg + 4 * j) * 32 + (bg + 8 * i);
                Psm[warp * 512 + o] = p[i * 4 + j];
            }
        }
        __syncthreads();

        #pragma unroll
        for (int k = 0; k < 4; ++k) {
            int r_loc = err + 4 * k;
            int o = r_loc * 32 + eb;
            float acc = 0.0f;
            acc = __fadd_rn(acc, Psm[0 * 512 + o]);
            acc = __fadd_rn(acc, Psm[1 * 512 + o]);
            acc = __fadd_rn(acc, Psm[2 * 512 + o]);
            acc = __fadd_rn(acc, Psm[3 * 512 + o]);
            float z = __fadd_rn(acc, uo[k]);
            float th = fast_tanh_B(z);
            float sn = do_upd(so[k], th);
            out[oidx[k]] = sn;
            snxt[eb * RR + rbase + r_loc] = sn;
        }

        // Grid barrier (CG pattern)
        __syncthreads();
        if (tid == 0) {
            asm volatile("red.release.gpu.global.add.u32 [%0], %1;"
                         :: "l"(&g_bar), "r"(1u) : "memory");
            unsigned target = (unsigned)(t + 1) * NCTA;
            unsigned v;
            do {
                asm volatile("ld.acquire.gpu.global.u32 %0, [%1];"
                             : "=r"(v) : "l"(&g_bar) : "memory");
                if (v >= target) break;
                __nanosleep(24);
            } while (true);
        }
        __syncthreads();

        par ^= 1;
    }
}

// ---------------------------------------------------------------------------
extern "C" void kernel_launch(void* const* d_in, const int* in_sizes, int n_in,
                              void* d_out, int out_size) {
    const float* x      = (const float*)d_in[0];
    const float* Win    = (const float*)d_in[1];
    const float* Wrec   = (const float*)d_in[2];
    const float* bias   = (const float*)d_in[3];
    const float* state0 = (const float*)d_in[4];
    float* out = (float*)d_out;

    int smem_gemm = (32 * XS_STRIDE + 64 * WS_STRIDE4) * 16;
    int smem_rec  = (16 * 512 + 4 * 1024) * 16;   // 128KB W + 64KB staging

    cudaFuncSetAttribute(input_gemm_strict, cudaFuncAttributeMaxDynamicSharedMemorySize, smem_gemm);
    cudaFuncSetAttribute(recurrent_kernel, cudaFuncAttributeMaxDynamicSharedMemorySize, smem_rec);

    input_gemm_strict<<<(BB * TT) / 32, 256, smem_gemm>>>(x, Win, bias, state0, out);

    recurrent_kernel<<<NCTA, NTHREADS, smem_rec>>>(Wrec, out);
}